// round 15
// baseline (speedup 1.0000x reference)
#include <cuda_runtime.h>
#include <cuda_fp16.h>
#include <cstdint>

#define C_IN   128
#define C_OUT  256
#define TAPS   4
#define N_MAX  262144
#define PADN_MAX (N_MAX + TAPS * 128)
#define BN_EPS 1e-4f
#define STAGE_B 8192               // one A or B conv stage: 128 rows x 64 bytes

// ---------------- device scratch ----------------
__device__ __half g_scratch[(size_t)PADN_MAX * C_OUT];  // contributions, fp16, perm order
__device__ __half g_xh[(size_t)N_MAX * C_IN];           // x converted to fp16
__device__ __half g_Bth[TAPS * C_OUT * C_IN];           // W as [tap][n][k], fp16
__device__ int   g_pslot[N_MAX * TAPS];                 // pslot[site*4+tap] = perm pos or -1
__device__ int   g_perm[PADN_MAX];                      // perm position -> input row
__device__ int   g_tap_count[TAPS];
__device__ int   g_pad_base[TAPS + 1];
__device__ int   g_tap_cursor[TAPS];
__device__ int   g_ctr;                                 // prep completion counter
__device__ float g_sum[C_OUT];
__device__ float g_sumsq[C_OUT];
__device__ float g_cnt;
__device__ float g_scale[C_OUT];
__device__ float g_bias[C_OUT];

// ---------------- helpers ----------------
__device__ __forceinline__ uint32_t smem_u32(const void* p) {
    uint32_t a;
    asm("{ .reg .u64 t; cvta.to.shared.u64 t, %1; cvt.u32.u64 %0, t; }" : "=r"(a) : "l"(p));
    return a;
}

#define CP_ASYNC(sa, ga) \
    asm volatile("cp.async.cg.shared.global [%0], [%1], 16;" :: "r"(sa), "l"(ga))
#define CP_ASYNC_Z(sa, ga, sz) \
    asm volatile("cp.async.cg.shared.global [%0], [%1], 16, %2;" :: "r"(sa), "l"(ga), "r"(sz))
#define CP_COMMIT() asm volatile("cp.async.commit_group;")
#define CP_WAIT(n)  asm volatile("cp.async.wait_group %0;" :: "n"(n))

__device__ __forceinline__ void ldsm_x4(uint32_t& r0, uint32_t& r1, uint32_t& r2,
                                        uint32_t& r3, uint32_t addr) {
    asm volatile("ldmatrix.sync.aligned.m8n8.x4.shared.b16 {%0,%1,%2,%3}, [%4];"
                 : "=r"(r0), "=r"(r1), "=r"(r2), "=r"(r3) : "r"(addr));
}
__device__ __forceinline__ void ldsm_x2(uint32_t& r0, uint32_t& r1, uint32_t addr) {
    asm volatile("ldmatrix.sync.aligned.m8n8.x2.shared.b16 {%0,%1}, [%2];"
                 : "=r"(r0), "=r"(r1) : "r"(addr));
}

#define MMA16(d, a, b0, b1)                                                         \
    asm volatile("mma.sync.aligned.m16n8k16.row.col.f32.f16.f16.f32 "               \
                 "{%0,%1,%2,%3},{%4,%5,%6,%7},{%8,%9},{%0,%1,%2,%3};"               \
                 : "+f"((d)[0]), "+f"((d)[1]), "+f"((d)[2]), "+f"((d)[3])           \
                 : "r"((a)[0]), "r"((a)[1]), "r"((a)[2]), "r"((a)[3]),              \
                   "r"(b0), "r"(b1))

// 16B shared load -> 8 floats (fp16 source)
__device__ __forceinline__ void lds_scratch8(uint32_t saddr, float* v) {
    uint32_t a, b, c, d;
    asm volatile("ld.shared.v4.u32 {%0,%1,%2,%3}, [%4];"
                 : "=r"(a), "=r"(b), "=r"(c), "=r"(d) : "r"(saddr));
    float2 f0 = __half22float2(*(__half2*)&a);
    float2 f1 = __half22float2(*(__half2*)&b);
    float2 f2 = __half22float2(*(__half2*)&c);
    float2 f3 = __half22float2(*(__half2*)&d);
    v[0] = f0.x; v[1] = f0.y; v[2] = f1.x; v[3] = f1.y;
    v[4] = f2.x; v[5] = f2.y; v[6] = f3.x; v[7] = f3.y;
}

// ---------------- K_prep: W->fp16, x->fp16, pslot=-1, histogram, last-block prefix -----
__global__ void k_prep(const float* __restrict__ x, const float* __restrict__ W,
                       const int* __restrict__ offset, int N) {
    const int gsz = gridDim.x * blockDim.x;
    const int gid = blockIdx.x * blockDim.x + threadIdx.x;

    for (int i = gid; i < TAPS * C_IN * C_OUT; i += gsz) {
        int t = i / (C_IN * C_OUT);
        int r = i % (C_IN * C_OUT);
        int k = r >> 8, n = r & 255;
        g_Bth[t * C_OUT * C_IN + n * C_IN + k] = __float2half_rn(W[i]);
    }
    for (int i = gid; i < N * TAPS; i += gsz) g_pslot[i] = -1;

    const float4* x4 = (const float4*)x;
    uint4* xo = (uint4*)g_xh;
    for (int i = gid; i < N * (C_IN / 8); i += gsz) {
        float4 v0 = x4[i * 2], v1 = x4[i * 2 + 1];
        __half2 h0 = __floats2half2_rn(v0.x, v0.y);
        __half2 h1 = __floats2half2_rn(v0.z, v0.w);
        __half2 h2 = __floats2half2_rn(v1.x, v1.y);
        __half2 h3 = __floats2half2_rn(v1.z, v1.w);
        uint4 o;
        o.x = *(uint32_t*)&h0; o.y = *(uint32_t*)&h1;
        o.z = *(uint32_t*)&h2; o.w = *(uint32_t*)&h3;
        xo[i] = o;
    }
    int c0 = 0, c1 = 0, c2 = 0, c3 = 0;
    for (int i = gid; i < N; i += gsz) {
        int k = offset[i];
        c0 += (k == 0); c1 += (k == 1); c2 += (k == 2); c3 += (k == 3);
    }
    c0 = __reduce_add_sync(0xffffffffu, c0);
    c1 = __reduce_add_sync(0xffffffffu, c1);
    c2 = __reduce_add_sync(0xffffffffu, c2);
    c3 = __reduce_add_sync(0xffffffffu, c3);
    if ((threadIdx.x & 31) == 0) {
        atomicAdd(&g_tap_count[0], c0);
        atomicAdd(&g_tap_count[1], c1);
        atomicAdd(&g_tap_count[2], c2);
        atomicAdd(&g_tap_count[3], c3);
    }
    __syncthreads();
    if (threadIdx.x == 0) {
        __threadfence();
        int done = atomicAdd(&g_ctr, 1);
        if (done == (int)gridDim.x - 1) {
            g_ctr = 0;                     // reset for next replay
            int b = 0;
            for (int t = 0; t < TAPS; t++) {
                g_pad_base[t]   = b;
                g_tap_cursor[t] = b;
                b += (g_tap_count[t] + 127) & ~127;
            }
            g_pad_base[TAPS] = b;
        }
    }
}

// ---------------- K_perm: permutation + inverse slot map + active count ----------------
__global__ void k_perm(const int* __restrict__ offset, const int* __restrict__ out_index,
                       const float* __restrict__ mask, int N) {
    int lane = threadIdx.x & 31;
    float cm = 0.f;
    for (int i = blockIdx.x * blockDim.x + threadIdx.x; i < N;
         i += gridDim.x * blockDim.x) {
        int k = offset[i];
        unsigned grp = __match_any_sync(0xffffffffu, k);
        int leader   = __ffs(grp) - 1;
        int rank     = __popc(grp & ((1u << lane) - 1u));
        int base = 0;
        if (lane == leader) base = atomicAdd(&g_tap_cursor[k], __popc(grp));
        base = __shfl_sync(0xffffffffu, base, leader);
        int pos = base + rank;
        g_perm[pos] = i;
        g_pslot[(size_t)out_index[i] * TAPS + k] = pos;
        cm += mask[i];
    }
#pragma unroll
    for (int o = 16; o; o >>= 1) cm += __shfl_xor_sync(0xffffffffu, cm, o);
    if ((threadIdx.x & 31) == 0) atomicAdd(&g_cnt, cm);
}

// ---------------- K_conv: fp16 GEMM, TWO row-tiles per block (R14 verbatim) ------------
#define SMEM_BYTES (1024 + 6 * STAGE_B)

__global__ __launch_bounds__(256, 2)
void k_conv() {
    extern __shared__ char smc[];
    int* srowA = (int*)smc;
    int* srowB = (int*)smc + 128;
    const uint32_t aBase = smem_u32(smc + 1024);
    const uint32_t bBase = aBase + 3 * STAGE_B;

    const int tid  = threadIdx.x;
    const int lane = tid & 31;
    const int wid  = tid >> 5;
    const int wm   = wid & 3;
    const int wn   = wid >> 2;
    const int padN = g_pad_base[TAPS];
    const int p0a  = (int)blockIdx.y * 256;
    if (p0a >= padN) return;
    const int p0b  = p0a + 128;
    const bool hasB = (p0b < padN);

    int tapA = 0, tapB = 0;
#pragma unroll
    for (int t = 1; t < TAPS; t++) {
        if (p0a >= g_pad_base[t]) tapA = t;
        if (p0b >= g_pad_base[t]) tapB = t;
    }

    const int colStart = (int)blockIdx.x * 128;
    const __half* BthA = g_Bth + (size_t)tapA * (C_OUT * C_IN);
    const __half* BthB = g_Bth + (size_t)tapB * (C_OUT * C_IN);

    if (tid < 128) {
        srowA[tid] = g_perm[p0a + tid];
    } else {
        srowB[tid - 128] = hasB ? g_perm[p0b + tid - 128] : 0;
    }
    __syncthreads();

    float acc[2][8][4];
#pragma unroll
    for (int i = 0; i < 2; i++)
#pragma unroll
        for (int j = 0; j < 8; j++)
#pragma unroll
            for (int q = 0; q < 4; q++) acc[i][j][q] = 0.f;

#define LOAD_CHUNK(c, SR, BT)                                                       \
    do {                                                                            \
        const int _k0 = ((c) & 3) * 32, _st = (c) % 3;                              \
        _Pragma("unroll")                                                           \
        for (int _u = 0; _u < 2; _u++) {                                            \
            int _seg = _u * 256 + tid;                                              \
            int _row = _seg >> 2, _q = _seg & 3;                                    \
            const __half* _ga = g_xh + (size_t)(SR)[_row] * C_IN + _k0 + _q * 8;    \
            uint32_t _da = aBase + _st * STAGE_B + _row * 64 +                      \
                           ((_q ^ ((_row >> 1) & 3)) << 4);                         \
            CP_ASYNC(_da, _ga);                                                     \
        }                                                                           \
        _Pragma("unroll")                                                           \
        for (int _u = 0; _u < 2; _u++) {                                            \
            int _seg = _u * 256 + tid;                                              \
            int _n = _seg >> 2, _q = _seg & 3;                                      \
            const __half* _gb = (BT) + (size_t)(colStart + _n) * C_IN + _k0 + _q * 8;\
            uint32_t _db = bBase + _st * STAGE_B + _n * 64 +                        \
                           ((_q ^ ((_n >> 1) & 3)) << 4);                           \
            CP_ASYNC(_db, _gb);                                                     \
        }                                                                           \
        CP_COMMIT();                                                                \
    } while (0)

#define COMPUTE(c)                                                                  \
    do {                                                                            \
        const uint32_t aSt = aBase + ((c) % 3) * STAGE_B;                           \
        const uint32_t bSt = bBase + ((c) % 3) * STAGE_B;                           \
        _Pragma("unroll")                                                           \
        for (int ks = 0; ks < 2; ks++) {                                            \
            const int kc = ks * 2;                                                  \
            uint32_t a[2][4];                                                       \
            _Pragma("unroll")                                                       \
            for (int i = 0; i < 2; i++) {                                           \
                int row = wm * 32 + i * 16 + (lane & 15);                           \
                int cch = kc + (lane >> 4);                                         \
                uint32_t ad = aSt + row * 64 + ((cch ^ ((row >> 1) & 3)) << 4);     \
                ldsm_x4(a[i][0], a[i][1], a[i][2], a[i][3], ad);                    \
            }                                                                       \
            _Pragma("unroll")                                                       \
            for (int j = 0; j < 8; j++) {                                           \
                int row = wn * 64 + j * 8 + (lane & 7);                             \
                int cch = kc + ((lane >> 3) & 1);                                   \
                uint32_t bd = bSt + row * 64 + ((cch ^ ((row >> 1) & 3)) << 4);     \
                uint32_t b0, b1;                                                    \
                ldsm_x2(b0, b1, bd);                                                \
                MMA16(acc[0][j], a[0], b0, b1);                                     \
                MMA16(acc[1][j], a[1], b0, b1);                                     \
            }                                                                       \
        }                                                                           \
    } while (0)

#define EPILOGUE(P0)                                                                \
    do {                                                                            \
        _Pragma("unroll")                                                           \
        for (int i = 0; i < 2; i++) {                                               \
            _Pragma("unroll")                                                       \
            for (int j = 0; j < 8; j++) {                                           \
                int rp = (P0) + wm * 32 + i * 16 + (lane >> 2);                     \
                int cg = colStart + wn * 64 + j * 8 + (lane & 3) * 2;               \
                __half2 h01 = __floats2half2_rn(acc[i][j][0], acc[i][j][1]);        \
                __half2 h23 = __floats2half2_rn(acc[i][j][2], acc[i][j][3]);        \
                *(__half2*)&g_scratch[(size_t)rp * C_OUT + cg] = h01;               \
                *(__half2*)&g_scratch[(size_t)(rp + 8) * C_OUT + cg] = h23;         \
            }                                                                       \
        }                                                                           \
    } while (0)

    LOAD_CHUNK(0, srowA, BthA);
    LOAD_CHUNK(1, srowA, BthA);
    LOAD_CHUNK(2, srowA, BthA);

    CP_WAIT(2); __syncthreads();
    COMPUTE(0); __syncthreads();
    LOAD_CHUNK(3, srowA, BthA);

    CP_WAIT(2); __syncthreads();
    COMPUTE(1); __syncthreads();
    LOAD_CHUNK(4, srowB, BthB);

    CP_WAIT(2); __syncthreads();
    COMPUTE(2); __syncthreads();
    LOAD_CHUNK(5, srowB, BthB);

    CP_WAIT(2); __syncthreads();
    COMPUTE(3);
    EPILOGUE(p0a);
#pragma unroll
    for (int i = 0; i < 2; i++)
#pragma unroll
        for (int j = 0; j < 8; j++)
#pragma unroll
            for (int q = 0; q < 4; q++) acc[i][j][q] = 0.f;
    __syncthreads();
    LOAD_CHUNK(6, srowB, BthB);

    CP_WAIT(2); __syncthreads();
    COMPUTE(4); __syncthreads();
    LOAD_CHUNK(7, srowB, BthB);

    CP_WAIT(2); __syncthreads();
    COMPUTE(5);

    CP_WAIT(1); __syncthreads();
    COMPUTE(6);

    CP_WAIT(0); __syncthreads();
    COMPUTE(7);

    if (hasB) EPILOGUE(p0b);
#undef LOAD_CHUNK
#undef COMPUTE
#undef EPILOGUE
}

// ---------------- K_cstats: cp.async-prefetched gather + per-channel stats -------------
// 256 sites/block in 16 batches of 16; double-buffered 32KB smem gather buffers.
#define CSB   256
#define BATCH 16
#define BUF_BYTES (2 * BATCH * TAPS * 512)   // 65536

__global__ __launch_bounds__(256)
void k_cstats(int N) {
    extern __shared__ char dsm[];            // 64KB gather buffers
    __shared__ int   sp[CSB * TAPS];
    __shared__ float ssum[C_OUT], ssq[C_OUT];
    const uint32_t bufu = smem_u32(dsm);

    const int tid  = threadIdx.x;
    const int lane = tid & 31;
    const int w    = tid >> 5;
    const int s0   = blockIdx.x * CSB;

    for (int i = tid; i < C_OUT; i += 256) { ssum[i] = 0.f; ssq[i] = 0.f; }
    for (int i = tid; i < CSB * TAPS; i += 256) {
        int site = s0 + (i >> 2);
        sp[i] = (site < N) ? g_pslot[(size_t)site * TAPS + (i & 3)] : -1;
    }
    __syncthreads();

#define PREFETCH(b)                                                                 \
    do {                                                                            \
        const uint32_t _off = ((b) & 1) * 32768u;                                   \
        _Pragma("unroll")                                                           \
        for (int _i = 0; _i < 8; _i++) {                                            \
            int _idx = _i * 256 + tid;                                              \
            int _row = _idx >> 5, _seg = _idx & 31;                                 \
            int _p = sp[(b) * 64 + _row];                                           \
            const char* _src = (const char*)(g_scratch + (size_t)(_p < 0 ? 0 : _p) * C_OUT) + _seg * 16; \
            CP_ASYNC_Z(bufu + _off + _row * 512 + _seg * 16, _src, _p < 0 ? 0 : 16);\
        }                                                                           \
        CP_COMMIT();                                                                \
    } while (0)

    float ls[8], lq[8];
#pragma unroll
    for (int c = 0; c < 8; c++) { ls[c] = 0.f; lq[c] = 0.f; }

    PREFETCH(0);
    for (int b = 0; b < 16; b++) {
        if (b < 15) { PREFETCH(b + 1); CP_WAIT(1); }
        else        { CP_WAIT(0); }
        __syncthreads();
        const uint32_t off = (b & 1) * 32768u;
#pragma unroll
        for (int s2 = 0; s2 < 2; s2++) {
            int slb = w * 2 + s2;            // site within batch
            float v[8];
#pragma unroll
            for (int c = 0; c < 8; c++) v[c] = 0.f;
#pragma unroll
            for (int t = 0; t < TAPS; t++) {
                float u[8];
                lds_scratch8(bufu + off + (slb * 4 + t) * 512 + lane * 16, u);
#pragma unroll
                for (int c = 0; c < 8; c++) v[c] += u[c];
            }
#pragma unroll
            for (int c = 0; c < 8; c++) { ls[c] += v[c]; lq[c] += v[c] * v[c]; }
        }
        __syncthreads();
    }
#pragma unroll
    for (int c = 0; c < 8; c++) {
        atomicAdd(&ssum[lane * 8 + c], ls[c]);
        atomicAdd(&ssq[lane * 8 + c], lq[c]);
    }
    __syncthreads();
    for (int i = tid; i < C_OUT; i += 256) {
        atomicAdd(&g_sum[i], ssum[i]);
        atomicAdd(&g_sumsq[i], ssq[i]);
    }
#undef PREFETCH
}

// ---------------- K_bn ----------------
__global__ void k_bn(const float* __restrict__ gamma, const float* __restrict__ beta) {
    int c = threadIdx.x;
    float cnt  = g_cnt;
    float mean = g_sum[c] / cnt;
    float var  = fmaxf(g_sumsq[c] / cnt - mean * mean, 0.f);
    float sc   = rsqrtf(var + BN_EPS) * gamma[c];
    float bi   = beta[c] - mean * sc;
    g_scale[c] = sc;
    g_bias[c]  = bi;
    g_sum[c]   = 0.f;
    g_sumsq[c] = 0.f;
    if (c == 0) g_cnt = 0.f;
    if (c < TAPS) g_tap_count[c] = 0;
}

// ---------------- K_final: cp.async-prefetched recombine + BN + ReLU + mask -> y -------
__global__ __launch_bounds__(256)
void k_final(float* __restrict__ y, const float* __restrict__ mask, int N) {
    extern __shared__ char dsm[];            // 64KB gather buffers
    __shared__ int sp[CSB * TAPS];
    const uint32_t bufu = smem_u32(dsm);

    const int tid  = threadIdx.x;
    const int lane = tid & 31;
    const int w    = tid >> 5;
    const int s0   = blockIdx.x * CSB;

    for (int i = tid; i < CSB * TAPS; i += 256) {
        int site = s0 + (i >> 2);
        sp[i] = (site < N) ? g_pslot[(size_t)site * TAPS + (i & 3)] : -1;
    }
    __syncthreads();

    float sc[8], bi[8];
    *(float4*)&sc[0] = *(const float4*)&g_scale[lane * 8];
    *(float4*)&sc[4] = *(const float4*)&g_scale[lane * 8 + 4];
    *(float4*)&bi[0] = *(const float4*)&g_bias[lane * 8];
    *(float4*)&bi[4] = *(const float4*)&g_bias[lane * 8 + 4];

#define PREFETCH(b)                                                                 \
    do {                                                                            \
        const uint32_t _off = ((b) & 1) * 32768u;                                   \
        _Pragma("unroll")                                                           \
        for (int _i = 0; _i < 8; _i++) {                                            \
            int _idx = _i * 256 + tid;                                              \
            int _row = _idx >> 5, _seg = _idx & 31;                                 \
            int _p = sp[(b) * 64 + _row];                                           \
            const char* _src = (const char*)(g_scratch + (size_t)(_p < 0 ? 0 : _p) * C_OUT) + _seg * 16; \
            CP_ASYNC_Z(bufu + _off + _row * 512 + _seg * 16, _src, _p < 0 ? 0 : 16);\
        }                                                                           \
        CP_COMMIT();                                                                \
    } while (0)

    PREFETCH(0);
    for (int b = 0; b < 16; b++) {
        if (b < 15) { PREFETCH(b + 1); CP_WAIT(1); }
        else        { CP_WAIT(0); }
        __syncthreads();
        const uint32_t off = (b & 1) * 32768u;
#pragma unroll
        for (int s2 = 0; s2 < 2; s2++) {
            int slb = w * 2 + s2;
            int site = s0 + b * 16 + slb;
            float v[8];
#pragma unroll
            for (int c = 0; c < 8; c++) v[c] = 0.f;
#pragma unroll
            for (int t = 0; t < TAPS; t++) {
                float u[8];
                lds_scratch8(bufu + off + (slb * 4 + t) * 512 + lane * 16, u);
#pragma unroll
                for (int c = 0; c < 8; c++) v[c] += u[c];
            }
            if (site < N) {
                float m = mask[site];
#pragma unroll
                for (int c = 0; c < 8; c++)
                    v[c] = fmaxf(fmaf(v[c], sc[c], bi[c]), 0.f) * m;
                float4* o = (float4*)(y + (size_t)site * C_OUT + lane * 8);
                o[0] = make_float4(v[0], v[1], v[2], v[3]);
                o[1] = make_float4(v[4], v[5], v[6], v[7]);
            }
        }
        __syncthreads();
    }
#undef PREFETCH
}

// ---------------- launch ----------------
extern "C" void kernel_launch(void* const* d_in, const int* in_sizes, int n_in,
                              void* d_out, int out_size) {
    const float* x         = (const float*)d_in[0];
    const float* W         = (const float*)d_in[1];
    const float* gamma     = (const float*)d_in[2];
    const float* beta      = (const float*)d_in[3];
    const int*   offset    = (const int*)d_in[4];
    const int*   out_index = (const int*)d_in[5];
    const float* mask      = (const float*)d_in[6];
    float*       out       = (float*)d_out;

    int N = in_sizes[4];
    if (N > N_MAX) N = N_MAX;

    cudaFuncSetAttribute(k_conv, cudaFuncAttributeMaxDynamicSharedMemorySize,
                         SMEM_BYTES);
    cudaFuncSetAttribute(k_cstats, cudaFuncAttributeMaxDynamicSharedMemorySize,
                         BUF_BYTES);
    cudaFuncSetAttribute(k_final, cudaFuncAttributeMaxDynamicSharedMemorySize,
                         BUF_BYTES);

    k_prep<<<512, 256>>>(x, W, offset, N);                                  // 0
    k_perm<<<256, 256>>>(offset, out_index, mask, N);                       // 1

    int tiles = (N + 127) / 128 + TAPS;   // upper bound incl. per-tap padding
    int pairTiles = (tiles + 1) / 2;
    k_conv<<<dim3(2, pairTiles), 256, SMEM_BYTES>>>();                      // 2

    int cb = (N + CSB - 1) / CSB;
    k_cstats<<<cb, 256, BUF_BYTES>>>(N);                                    // 3
    k_bn<<<1, 256>>>(gamma, beta);                                          // 4
    k_final<<<cb, 256, BUF_BYTES>>>(out, mask, N);                          // 5  <- ncu -s 5
}

// round 16
// speedup vs baseline: 1.1937x; 1.1937x over previous
#include <cuda_runtime.h>
#include <cuda_fp16.h>
#include <cstdint>

#define C_IN   128
#define C_OUT  256
#define TAPS   4
#define N_MAX  262144
#define PADN_MAX (N_MAX + TAPS * 128)
#define BN_EPS 1e-4f
#define STAGE_B 8192               // one A or B conv stage: 128 rows x 64 bytes

// ---------------- device scratch ----------------
__device__ __half g_scratch[(size_t)PADN_MAX * C_OUT];  // contributions, fp16, perm order
__device__ __half g_xh[(size_t)N_MAX * C_IN];           // x converted to fp16
__device__ __half g_Bth[TAPS * C_OUT * C_IN];           // W as [tap][n][k], fp16
__device__ int   g_pslot[N_MAX * TAPS];                 // pslot[site*4+tap] = perm pos or -1
__device__ int   g_perm[PADN_MAX];                      // perm position -> input row
__device__ int   g_tap_count[TAPS];
__device__ int   g_pad_base[TAPS + 1];
__device__ int   g_tap_cursor[TAPS];
__device__ int   g_ctr;                                 // prep completion counter
__device__ float g_sum[C_OUT];
__device__ float g_sumsq[C_OUT];
__device__ float g_cnt;
__device__ float g_scale[C_OUT];
__device__ float g_bias[C_OUT];

// ---------------- helpers ----------------
__device__ __forceinline__ uint32_t smem_u32(const void* p) {
    uint32_t a;
    asm("{ .reg .u64 t; cvta.to.shared.u64 t, %1; cvt.u32.u64 %0, t; }" : "=r"(a) : "l"(p));
    return a;
}

#define CP_ASYNC(sa, ga) \
    asm volatile("cp.async.cg.shared.global [%0], [%1], 16;" :: "r"(sa), "l"(ga))
#define CP_COMMIT() asm volatile("cp.async.commit_group;")
#define CP_WAIT(n)  asm volatile("cp.async.wait_group %0;" :: "n"(n))

__device__ __forceinline__ void ldsm_x4(uint32_t& r0, uint32_t& r1, uint32_t& r2,
                                        uint32_t& r3, uint32_t addr) {
    asm volatile("ldmatrix.sync.aligned.m8n8.x4.shared.b16 {%0,%1,%2,%3}, [%4];"
                 : "=r"(r0), "=r"(r1), "=r"(r2), "=r"(r3) : "r"(addr));
}
__device__ __forceinline__ void ldsm_x2(uint32_t& r0, uint32_t& r1, uint32_t addr) {
    asm volatile("ldmatrix.sync.aligned.m8n8.x2.shared.b16 {%0,%1}, [%2];"
                 : "=r"(r0), "=r"(r1) : "r"(addr));
}

#define MMA16(d, a, b0, b1)                                                         \
    asm volatile("mma.sync.aligned.m16n8k16.row.col.f32.f16.f16.f32 "               \
                 "{%0,%1,%2,%3},{%4,%5,%6,%7},{%8,%9},{%0,%1,%2,%3};"               \
                 : "+f"((d)[0]), "+f"((d)[1]), "+f"((d)[2]), "+f"((d)[3])           \
                 : "r"((a)[0]), "r"((a)[1]), "r"((a)[2]), "r"((a)[3]),              \
                   "r"(b0), "r"(b1))

// read 4 channels (two half2) as floats
__device__ __forceinline__ float4 ld_scratch4(const __half* p) {
    uint2 u = *(const uint2*)p;
    float2 fa = __half22float2(*(__half2*)&u.x);
    float2 fb = __half22float2(*(__half2*)&u.y);
    return make_float4(fa.x, fa.y, fb.x, fb.y);
}

// ---------------- K_prep: W->fp16, x->fp16, pslot=-1, histogram, last-block prefix -----
__global__ void k_prep(const float* __restrict__ x, const float* __restrict__ W,
                       const int* __restrict__ offset, int N) {
    const int gsz = gridDim.x * blockDim.x;
    const int gid = blockIdx.x * blockDim.x + threadIdx.x;

    for (int i = gid; i < TAPS * C_IN * C_OUT; i += gsz) {
        int t = i / (C_IN * C_OUT);
        int r = i % (C_IN * C_OUT);
        int k = r >> 8, n = r & 255;
        g_Bth[t * C_OUT * C_IN + n * C_IN + k] = __float2half_rn(W[i]);
    }
    for (int i = gid; i < N * TAPS; i += gsz) g_pslot[i] = -1;

    const float4* x4 = (const float4*)x;
    uint4* xo = (uint4*)g_xh;
    for (int i = gid; i < N * (C_IN / 8); i += gsz) {
        float4 v0 = x4[i * 2], v1 = x4[i * 2 + 1];
        __half2 h0 = __floats2half2_rn(v0.x, v0.y);
        __half2 h1 = __floats2half2_rn(v0.z, v0.w);
        __half2 h2 = __floats2half2_rn(v1.x, v1.y);
        __half2 h3 = __floats2half2_rn(v1.z, v1.w);
        uint4 o;
        o.x = *(uint32_t*)&h0; o.y = *(uint32_t*)&h1;
        o.z = *(uint32_t*)&h2; o.w = *(uint32_t*)&h3;
        xo[i] = o;
    }
    int c0 = 0, c1 = 0, c2 = 0, c3 = 0;
    for (int i = gid; i < N; i += gsz) {
        int k = offset[i];
        c0 += (k == 0); c1 += (k == 1); c2 += (k == 2); c3 += (k == 3);
    }
    c0 = __reduce_add_sync(0xffffffffu, c0);
    c1 = __reduce_add_sync(0xffffffffu, c1);
    c2 = __reduce_add_sync(0xffffffffu, c2);
    c3 = __reduce_add_sync(0xffffffffu, c3);
    if ((threadIdx.x & 31) == 0) {
        atomicAdd(&g_tap_count[0], c0);
        atomicAdd(&g_tap_count[1], c1);
        atomicAdd(&g_tap_count[2], c2);
        atomicAdd(&g_tap_count[3], c3);
    }
    __syncthreads();
    if (threadIdx.x == 0) {
        __threadfence();
        int done = atomicAdd(&g_ctr, 1);
        if (done == (int)gridDim.x - 1) {
            g_ctr = 0;                     // reset for next replay
            int b = 0;
            for (int t = 0; t < TAPS; t++) {
                g_pad_base[t]   = b;
                g_tap_cursor[t] = b;
                b += (g_tap_count[t] + 127) & ~127;
            }
            g_pad_base[TAPS] = b;
        }
    }
}

// ---------------- K_perm: permutation + inverse slot map + active count ----------------
__global__ void k_perm(const int* __restrict__ offset, const int* __restrict__ out_index,
                       const float* __restrict__ mask, int N) {
    int lane = threadIdx.x & 31;
    float cm = 0.f;
    for (int i = blockIdx.x * blockDim.x + threadIdx.x; i < N;
         i += gridDim.x * blockDim.x) {
        int k = offset[i];
        unsigned grp = __match_any_sync(0xffffffffu, k);
        int leader   = __ffs(grp) - 1;
        int rank     = __popc(grp & ((1u << lane) - 1u));
        int base = 0;
        if (lane == leader) base = atomicAdd(&g_tap_cursor[k], __popc(grp));
        base = __shfl_sync(0xffffffffu, base, leader);
        int pos = base + rank;
        g_perm[pos] = i;
        g_pslot[(size_t)out_index[i] * TAPS + k] = pos;
        cm += mask[i];
    }
#pragma unroll
    for (int o = 16; o; o >>= 1) cm += __shfl_xor_sync(0xffffffffu, cm, o);
    if ((threadIdx.x & 31) == 0) atomicAdd(&g_cnt, cm);
}

// ---------------- K_conv: fp16 GEMM, TWO row-tiles per block (R14 verbatim) ------------
#define SMEM_BYTES (1024 + 6 * STAGE_B)

__global__ __launch_bounds__(256, 2)
void k_conv() {
    extern __shared__ char smc[];
    int* srowA = (int*)smc;
    int* srowB = (int*)smc + 128;
    const uint32_t aBase = smem_u32(smc + 1024);
    const uint32_t bBase = aBase + 3 * STAGE_B;

    const int tid  = threadIdx.x;
    const int lane = tid & 31;
    const int wid  = tid >> 5;
    const int wm   = wid & 3;
    const int wn   = wid >> 2;
    const int padN = g_pad_base[TAPS];
    const int p0a  = (int)blockIdx.y * 256;
    if (p0a >= padN) return;
    const int p0b  = p0a + 128;
    const bool hasB = (p0b < padN);

    int tapA = 0, tapB = 0;
#pragma unroll
    for (int t = 1; t < TAPS; t++) {
        if (p0a >= g_pad_base[t]) tapA = t;
        if (p0b >= g_pad_base[t]) tapB = t;
    }

    const int colStart = (int)blockIdx.x * 128;
    const __half* BthA = g_Bth + (size_t)tapA * (C_OUT * C_IN);
    const __half* BthB = g_Bth + (size_t)tapB * (C_OUT * C_IN);

    if (tid < 128) {
        srowA[tid] = g_perm[p0a + tid];
    } else {
        srowB[tid - 128] = hasB ? g_perm[p0b + tid - 128] : 0;
    }
    __syncthreads();

    float acc[2][8][4];
#pragma unroll
    for (int i = 0; i < 2; i++)
#pragma unroll
        for (int j = 0; j < 8; j++)
#pragma unroll
            for (int q = 0; q < 4; q++) acc[i][j][q] = 0.f;

#define LOAD_CHUNK(c, SR, BT)                                                       \
    do {                                                                            \
        const int _k0 = ((c) & 3) * 32, _st = (c) % 3;                              \
        _Pragma("unroll")                                                           \
        for (int _u = 0; _u < 2; _u++) {                                            \
            int _seg = _u * 256 + tid;                                              \
            int _row = _seg >> 2, _q = _seg & 3;                                    \
            const __half* _ga = g_xh + (size_t)(SR)[_row] * C_IN + _k0 + _q * 8;    \
            uint32_t _da = aBase + _st * STAGE_B + _row * 64 +                      \
                           ((_q ^ ((_row >> 1) & 3)) << 4);                         \
            CP_ASYNC(_da, _ga);                                                     \
        }                                                                           \
        _Pragma("unroll")                                                           \
        for (int _u = 0; _u < 2; _u++) {                                            \
            int _seg = _u * 256 + tid;                                              \
            int _n = _seg >> 2, _q = _seg & 3;                                      \
            const __half* _gb = (BT) + (size_t)(colStart + _n) * C_IN + _k0 + _q * 8;\
            uint32_t _db = bBase + _st * STAGE_B + _n * 64 +                        \
                           ((_q ^ ((_n >> 1) & 3)) << 4);                           \
            CP_ASYNC(_db, _gb);                                                     \
        }                                                                           \
        CP_COMMIT();                                                                \
    } while (0)

#define COMPUTE(c)                                                                  \
    do {                                                                            \
        const uint32_t aSt = aBase + ((c) % 3) * STAGE_B;                           \
        const uint32_t bSt = bBase + ((c) % 3) * STAGE_B;                           \
        _Pragma("unroll")                                                           \
        for (int ks = 0; ks < 2; ks++) {                                            \
            const int kc = ks * 2;                                                  \
            uint32_t a[2][4];                                                       \
            _Pragma("unroll")                                                       \
            for (int i = 0; i < 2; i++) {                                           \
                int row = wm * 32 + i * 16 + (lane & 15);                           \
                int cch = kc + (lane >> 4);                                         \
                uint32_t ad = aSt + row * 64 + ((cch ^ ((row >> 1) & 3)) << 4);     \
                ldsm_x4(a[i][0], a[i][1], a[i][2], a[i][3], ad);                    \
            }                                                                       \
            _Pragma("unroll")                                                       \
            for (int j = 0; j < 8; j++) {                                           \
                int row = wn * 64 + j * 8 + (lane & 7);                             \
                int cch = kc + ((lane >> 3) & 1);                                   \
                uint32_t bd = bSt + row * 64 + ((cch ^ ((row >> 1) & 3)) << 4);     \
                uint32_t b0, b1;                                                    \
                ldsm_x2(b0, b1, bd);                                                \
                MMA16(acc[0][j], a[0], b0, b1);                                     \
                MMA16(acc[1][j], a[1], b0, b1);                                     \
            }                                                                       \
        }                                                                           \
    } while (0)

#define EPILOGUE(P0)                                                                \
    do {                                                                            \
        _Pragma("unroll")                                                           \
        for (int i = 0; i < 2; i++) {                                               \
            _Pragma("unroll")                                                       \
            for (int j = 0; j < 8; j++) {                                           \
                int rp = (P0) + wm * 32 + i * 16 + (lane >> 2);                     \
                int cg = colStart + wn * 64 + j * 8 + (lane & 3) * 2;               \
                __half2 h01 = __floats2half2_rn(acc[i][j][0], acc[i][j][1]);        \
                __half2 h23 = __floats2half2_rn(acc[i][j][2], acc[i][j][3]);        \
                *(__half2*)&g_scratch[(size_t)rp * C_OUT + cg] = h01;               \
                *(__half2*)&g_scratch[(size_t)(rp + 8) * C_OUT + cg] = h23;         \
            }                                                                       \
        }                                                                           \
    } while (0)

    LOAD_CHUNK(0, srowA, BthA);
    LOAD_CHUNK(1, srowA, BthA);
    LOAD_CHUNK(2, srowA, BthA);

    CP_WAIT(2); __syncthreads();
    COMPUTE(0); __syncthreads();
    LOAD_CHUNK(3, srowA, BthA);

    CP_WAIT(2); __syncthreads();
    COMPUTE(1); __syncthreads();
    LOAD_CHUNK(4, srowB, BthB);

    CP_WAIT(2); __syncthreads();
    COMPUTE(2); __syncthreads();
    LOAD_CHUNK(5, srowB, BthB);

    CP_WAIT(2); __syncthreads();
    COMPUTE(3);
    EPILOGUE(p0a);
#pragma unroll
    for (int i = 0; i < 2; i++)
#pragma unroll
        for (int j = 0; j < 8; j++)
#pragma unroll
            for (int q = 0; q < 4; q++) acc[i][j][q] = 0.f;
    __syncthreads();
    LOAD_CHUNK(6, srowB, BthB);

    CP_WAIT(2); __syncthreads();
    COMPUTE(4); __syncthreads();
    LOAD_CHUNK(7, srowB, BthB);

    CP_WAIT(2); __syncthreads();
    COMPUTE(5);

    CP_WAIT(1); __syncthreads();
    COMPUTE(6);

    CP_WAIT(0); __syncthreads();
    COMPUTE(7);

    if (hasB) EPILOGUE(p0b);
#undef LOAD_CHUNK
#undef COMPUTE
#undef EPILOGUE
}

// ---------------- K_cstats: combine (discard) + per-channel stats (R14 verbatim) -------
#define SITES_PER_BLOCK 256
__global__ __launch_bounds__(256)
void k_cstats(int N) {
    __shared__ int   sp[SITES_PER_BLOCK * TAPS];   // 4 KB
    __shared__ float ssum[C_OUT], ssq[C_OUT];
    const int tid = threadIdx.x;
    const int s0  = blockIdx.x * SITES_PER_BLOCK;

    for (int i = tid; i < C_OUT; i += 256) { ssum[i] = 0.f; ssq[i] = 0.f; }
    for (int i = tid; i < SITES_PER_BLOCK * TAPS; i += 256) {
        int site = s0 + (i >> 2);
        sp[i] = (site < N) ? g_pslot[(size_t)site * TAPS + (i & 3)] : -1;
    }
    __syncthreads();

    const int c4 = tid & 63, sr = tid >> 6;
    float ls0 = 0.f, ls1 = 0.f, ls2 = 0.f, ls3 = 0.f;
    float lq0 = 0.f, lq1 = 0.f, lq2 = 0.f, lq3 = 0.f;

    for (int it = 0; it < SITES_PER_BLOCK / 4; it++) {
        int sl = it * 4 + sr;
        float4 v = make_float4(0.f, 0.f, 0.f, 0.f);
#pragma unroll
        for (int t = 0; t < TAPS; t++) {
            int p = sp[sl * 4 + t];
            if (p >= 0) {
                float4 u = ld_scratch4(g_scratch + (size_t)p * C_OUT + c4 * 4);
                v.x += u.x; v.y += u.y; v.z += u.z; v.w += u.w;
            }
        }
        ls0 += v.x; ls1 += v.y; ls2 += v.z; ls3 += v.w;
        lq0 += v.x * v.x; lq1 += v.y * v.y; lq2 += v.z * v.z; lq3 += v.w * v.w;
    }
    atomicAdd(&ssum[c4 * 4 + 0], ls0);
    atomicAdd(&ssum[c4 * 4 + 1], ls1);
    atomicAdd(&ssum[c4 * 4 + 2], ls2);
    atomicAdd(&ssum[c4 * 4 + 3], ls3);
    atomicAdd(&ssq[c4 * 4 + 0], lq0);
    atomicAdd(&ssq[c4 * 4 + 1], lq1);
    atomicAdd(&ssq[c4 * 4 + 2], lq2);
    atomicAdd(&ssq[c4 * 4 + 3], lq3);
    __syncthreads();
    for (int i = tid; i < C_OUT; i += 256) {
        atomicAdd(&g_sum[i], ssum[i]);
        atomicAdd(&g_sumsq[i], ssq[i]);
    }
}

// ---------------- K_bn ----------------
__global__ void k_bn(const float* __restrict__ gamma, const float* __restrict__ beta) {
    int c = threadIdx.x;
    float cnt  = g_cnt;
    float mean = g_sum[c] / cnt;
    float var  = fmaxf(g_sumsq[c] / cnt - mean * mean, 0.f);
    float sc   = rsqrtf(var + BN_EPS) * gamma[c];
    float bi   = beta[c] - mean * sc;
    g_scale[c] = sc;
    g_bias[c]  = bi;
    g_sum[c]   = 0.f;
    g_sumsq[c] = 0.f;
    if (c == 0) g_cnt = 0.f;
    if (c < TAPS) g_tap_count[c] = 0;
}

// ---------------- K_final: recombine + BN + ReLU + mask -> y (R14 verbatim) ------------
__global__ __launch_bounds__(256)
void k_final(float* __restrict__ y, const float* __restrict__ mask, int N) {
    __shared__ int sp[SITES_PER_BLOCK * TAPS];
    const int tid = threadIdx.x;
    const int s0  = blockIdx.x * SITES_PER_BLOCK;

    for (int i = tid; i < SITES_PER_BLOCK * TAPS; i += 256) {
        int site = s0 + (i >> 2);
        sp[i] = (site < N) ? g_pslot[(size_t)site * TAPS + (i & 3)] : -1;
    }
    __syncthreads();

    const int c4 = tid & 63, sr = tid >> 6;
    const float4 sc = *(const float4*)&g_scale[c4 * 4];
    const float4 bi = *(const float4*)&g_bias[c4 * 4];

    for (int it = 0; it < SITES_PER_BLOCK / 4; it++) {
        int sl = it * 4 + sr;
        int site = s0 + sl;
        if (site >= N) continue;
        float4 v = make_float4(0.f, 0.f, 0.f, 0.f);
#pragma unroll
        for (int t = 0; t < TAPS; t++) {
            int p = sp[sl * 4 + t];
            if (p >= 0) {
                float4 u = ld_scratch4(g_scratch + (size_t)p * C_OUT + c4 * 4);
                v.x += u.x; v.y += u.y; v.z += u.z; v.w += u.w;
            }
        }
        float m = mask[site];
        v.x = fmaxf(fmaf(v.x, sc.x, bi.x), 0.f) * m;
        v.y = fmaxf(fmaf(v.y, sc.y, bi.y), 0.f) * m;
        v.z = fmaxf(fmaf(v.z, sc.z, bi.z), 0.f) * m;
        v.w = fmaxf(fmaf(v.w, sc.w, bi.w), 0.f) * m;
        *(float4*)&y[(size_t)site * C_OUT + c4 * 4] = v;
    }
}

// ---------------- launch ----------------
extern "C" void kernel_launch(void* const* d_in, const int* in_sizes, int n_in,
                              void* d_out, int out_size) {
    const float* x         = (const float*)d_in[0];
    const float* W         = (const float*)d_in[1];
    const float* gamma     = (const float*)d_in[2];
    const float* beta      = (const float*)d_in[3];
    const int*   offset    = (const int*)d_in[4];
    const int*   out_index = (const int*)d_in[5];
    const float* mask      = (const float*)d_in[6];
    float*       out       = (float*)d_out;

    int N = in_sizes[4];
    if (N > N_MAX) N = N_MAX;

    cudaFuncSetAttribute(k_conv, cudaFuncAttributeMaxDynamicSharedMemorySize,
                         SMEM_BYTES);

    k_prep<<<512, 256>>>(x, W, offset, N);                                  // 0
    k_perm<<<256, 256>>>(offset, out_index, mask, N);                       // 1

    int tiles = (N + 127) / 128 + TAPS;   // upper bound incl. per-tap padding
    int pairTiles = (tiles + 1) / 2;
    k_conv<<<dim3(2, pairTiles), 256, SMEM_BYTES>>>();                      // 2

    int cb = (N + SITES_PER_BLOCK - 1) / SITES_PER_BLOCK;
    k_cstats<<<cb, 256>>>(N);                                               // 3
    k_bn<<<1, 256>>>(gamma, beta);                                          // 4
    k_final<<<cb, 256>>>(out, mask, N);                                     // 5  <- ncu -s 5
}

// round 17
// speedup vs baseline: 1.2013x; 1.0063x over previous
#include <cuda_runtime.h>
#include <cuda_fp16.h>
#include <cstdint>

#define C_IN   128
#define C_OUT  256
#define TAPS   4
#define N_MAX  262144
#define PADN_MAX (N_MAX + TAPS * 128)
#define BN_EPS 1e-4f
#define STAGE_B 8192               // one A or B conv stage: 128 rows x 64 bytes

// ---------------- device scratch ----------------
__device__ __half g_scratch[(size_t)PADN_MAX * C_OUT];  // contributions, fp16, perm order
__device__ __half g_xh[(size_t)N_MAX * C_IN];           // x converted to fp16
__device__ __half g_Bth[TAPS * C_OUT * C_IN];           // W as [tap][n][k], fp16
__device__ int   g_pslot[N_MAX * TAPS];                 // pslot[site*4+tap] = perm pos or -1
__device__ int   g_perm[PADN_MAX];                      // perm position -> input row
__device__ int   g_tap_count[TAPS];
__device__ int   g_pad_base[TAPS + 1];
__device__ int   g_tap_cursor[TAPS];
__device__ int   g_ctr;                                 // prep completion counter
__device__ int   g_ctr2;                                // cstats completion counter
__device__ float g_sum[C_OUT];
__device__ float g_sumsq[C_OUT];
__device__ float g_cnt;
__device__ float g_scale[C_OUT];
__device__ float g_bias[C_OUT];

// ---------------- helpers ----------------
__device__ __forceinline__ uint32_t smem_u32(const void* p) {
    uint32_t a;
    asm("{ .reg .u64 t; cvta.to.shared.u64 t, %1; cvt.u32.u64 %0, t; }" : "=r"(a) : "l"(p));
    return a;
}

#define CP_ASYNC(sa, ga) \
    asm volatile("cp.async.cg.shared.global [%0], [%1], 16;" :: "r"(sa), "l"(ga))
#define CP_COMMIT() asm volatile("cp.async.commit_group;")
#define CP_WAIT(n)  asm volatile("cp.async.wait_group %0;" :: "n"(n))

__device__ __forceinline__ void ldsm_x4(uint32_t& r0, uint32_t& r1, uint32_t& r2,
                                        uint32_t& r3, uint32_t addr) {
    asm volatile("ldmatrix.sync.aligned.m8n8.x4.shared.b16 {%0,%1,%2,%3}, [%4];"
                 : "=r"(r0), "=r"(r1), "=r"(r2), "=r"(r3) : "r"(addr));
}
__device__ __forceinline__ void ldsm_x2(uint32_t& r0, uint32_t& r1, uint32_t addr) {
    asm volatile("ldmatrix.sync.aligned.m8n8.x2.shared.b16 {%0,%1}, [%2];"
                 : "=r"(r0), "=r"(r1) : "r"(addr));
}

#define MMA16(d, a, b0, b1)                                                         \
    asm volatile("mma.sync.aligned.m16n8k16.row.col.f32.f16.f16.f32 "               \
                 "{%0,%1,%2,%3},{%4,%5,%6,%7},{%8,%9},{%0,%1,%2,%3};"               \
                 : "+f"((d)[0]), "+f"((d)[1]), "+f"((d)[2]), "+f"((d)[3])           \
                 : "r"((a)[0]), "r"((a)[1]), "r"((a)[2]), "r"((a)[3]),              \
                   "r"(b0), "r"(b1))

// read 4 channels (two half2) as floats
__device__ __forceinline__ float4 ld_scratch4(const __half* p) {
    uint2 u = *(const uint2*)p;
    float2 fa = __half22float2(*(__half2*)&u.x);
    float2 fb = __half22float2(*(__half2*)&u.y);
    return make_float4(fa.x, fa.y, fb.x, fb.y);
}

// ---------------- K_prep: W->fp16, x->fp16, pslot=-1, histogram, last-block prefix -----
__global__ void k_prep(const float* __restrict__ x, const float* __restrict__ W,
                       const int* __restrict__ offset, int N) {
    const int gsz = gridDim.x * blockDim.x;
    const int gid = blockIdx.x * blockDim.x + threadIdx.x;

    for (int i = gid; i < TAPS * C_IN * C_OUT; i += gsz) {
        int t = i / (C_IN * C_OUT);
        int r = i % (C_IN * C_OUT);
        int k = r >> 8, n = r & 255;
        g_Bth[t * C_OUT * C_IN + n * C_IN + k] = __float2half_rn(W[i]);
    }
    // vectorized pslot init (N*TAPS divisible by 4)
    int4* ps4 = (int4*)g_pslot;
    const int4 m1 = make_int4(-1, -1, -1, -1);
    for (int i = gid; i < N; i += gsz) ps4[i] = m1;

    const float4* x4 = (const float4*)x;
    uint4* xo = (uint4*)g_xh;
    for (int i = gid; i < N * (C_IN / 8); i += gsz) {
        float4 v0 = x4[i * 2], v1 = x4[i * 2 + 1];
        __half2 h0 = __floats2half2_rn(v0.x, v0.y);
        __half2 h1 = __floats2half2_rn(v0.z, v0.w);
        __half2 h2 = __floats2half2_rn(v1.x, v1.y);
        __half2 h3 = __floats2half2_rn(v1.z, v1.w);
        uint4 o;
        o.x = *(uint32_t*)&h0; o.y = *(uint32_t*)&h1;
        o.z = *(uint32_t*)&h2; o.w = *(uint32_t*)&h3;
        xo[i] = o;
    }
    int c0 = 0, c1 = 0, c2 = 0, c3 = 0;
    for (int i = gid; i < N; i += gsz) {
        int k = offset[i];
        c0 += (k == 0); c1 += (k == 1); c2 += (k == 2); c3 += (k == 3);
    }
    c0 = __reduce_add_sync(0xffffffffu, c0);
    c1 = __reduce_add_sync(0xffffffffu, c1);
    c2 = __reduce_add_sync(0xffffffffu, c2);
    c3 = __reduce_add_sync(0xffffffffu, c3);
    if ((threadIdx.x & 31) == 0) {
        atomicAdd(&g_tap_count[0], c0);
        atomicAdd(&g_tap_count[1], c1);
        atomicAdd(&g_tap_count[2], c2);
        atomicAdd(&g_tap_count[3], c3);
    }
    __syncthreads();
    if (threadIdx.x == 0) {
        __threadfence();
        int done = atomicAdd(&g_ctr, 1);
        if (done == (int)gridDim.x - 1) {
            g_ctr = 0;                     // reset for next replay
            int b = 0;
            for (int t = 0; t < TAPS; t++) {
                g_pad_base[t]   = b;
                g_tap_cursor[t] = b;
                b += (g_tap_count[t] + 127) & ~127;
            }
            g_pad_base[TAPS] = b;
        }
    }
}

// ---------------- K_perm: permutation + inverse slot map + active count ----------------
__global__ void k_perm(const int* __restrict__ offset, const int* __restrict__ out_index,
                       const float* __restrict__ mask, int N) {
    int lane = threadIdx.x & 31;
    float cm = 0.f;
    for (int i = blockIdx.x * blockDim.x + threadIdx.x; i < N;
         i += gridDim.x * blockDim.x) {
        int k = offset[i];
        unsigned grp = __match_any_sync(0xffffffffu, k);
        int leader   = __ffs(grp) - 1;
        int rank     = __popc(grp & ((1u << lane) - 1u));
        int base = 0;
        if (lane == leader) base = atomicAdd(&g_tap_cursor[k], __popc(grp));
        base = __shfl_sync(0xffffffffu, base, leader);
        int pos = base + rank;
        g_perm[pos] = i;
        g_pslot[(size_t)out_index[i] * TAPS + k] = pos;
        cm += mask[i];
    }
#pragma unroll
    for (int o = 16; o; o >>= 1) cm += __shfl_xor_sync(0xffffffffu, cm, o);
    if ((threadIdx.x & 31) == 0) atomicAdd(&g_cnt, cm);
}

// ---------------- K_conv: fp16 GEMM, TWO row-tiles per block (R14 verbatim) ------------
#define SMEM_BYTES (1024 + 6 * STAGE_B)

__global__ __launch_bounds__(256, 2)
void k_conv() {
    extern __shared__ char smc[];
    int* srowA = (int*)smc;
    int* srowB = (int*)smc + 128;
    const uint32_t aBase = smem_u32(smc + 1024);
    const uint32_t bBase = aBase + 3 * STAGE_B;

    const int tid  = threadIdx.x;
    const int lane = tid & 31;
    const int wid  = tid >> 5;
    const int wm   = wid & 3;
    const int wn   = wid >> 2;
    const int padN = g_pad_base[TAPS];
    const int p0a  = (int)blockIdx.y * 256;
    if (p0a >= padN) return;
    const int p0b  = p0a + 128;
    const bool hasB = (p0b < padN);

    int tapA = 0, tapB = 0;
#pragma unroll
    for (int t = 1; t < TAPS; t++) {
        if (p0a >= g_pad_base[t]) tapA = t;
        if (p0b >= g_pad_base[t]) tapB = t;
    }

    const int colStart = (int)blockIdx.x * 128;
    const __half* BthA = g_Bth + (size_t)tapA * (C_OUT * C_IN);
    const __half* BthB = g_Bth + (size_t)tapB * (C_OUT * C_IN);

    if (tid < 128) {
        srowA[tid] = g_perm[p0a + tid];
    } else {
        srowB[tid - 128] = hasB ? g_perm[p0b + tid - 128] : 0;
    }
    __syncthreads();

    float acc[2][8][4];
#pragma unroll
    for (int i = 0; i < 2; i++)
#pragma unroll
        for (int j = 0; j < 8; j++)
#pragma unroll
            for (int q = 0; q < 4; q++) acc[i][j][q] = 0.f;

#define LOAD_CHUNK(c, SR, BT)                                                       \
    do {                                                                            \
        const int _k0 = ((c) & 3) * 32, _st = (c) % 3;                              \
        _Pragma("unroll")                                                           \
        for (int _u = 0; _u < 2; _u++) {                                            \
            int _seg = _u * 256 + tid;                                              \
            int _row = _seg >> 2, _q = _seg & 3;                                    \
            const __half* _ga = g_xh + (size_t)(SR)[_row] * C_IN + _k0 + _q * 8;    \
            uint32_t _da = aBase + _st * STAGE_B + _row * 64 +                      \
                           ((_q ^ ((_row >> 1) & 3)) << 4);                         \
            CP_ASYNC(_da, _ga);                                                     \
        }                                                                           \
        _Pragma("unroll")                                                           \
        for (int _u = 0; _u < 2; _u++) {                                            \
            int _seg = _u * 256 + tid;                                              \
            int _n = _seg >> 2, _q = _seg & 3;                                      \
            const __half* _gb = (BT) + (size_t)(colStart + _n) * C_IN + _k0 + _q * 8;\
            uint32_t _db = bBase + _st * STAGE_B + _n * 64 +                        \
                           ((_q ^ ((_n >> 1) & 3)) << 4);                           \
            CP_ASYNC(_db, _gb);                                                     \
        }                                                                           \
        CP_COMMIT();                                                                \
    } while (0)

#define COMPUTE(c)                                                                  \
    do {                                                                            \
        const uint32_t aSt = aBase + ((c) % 3) * STAGE_B;                           \
        const uint32_t bSt = bBase + ((c) % 3) * STAGE_B;                           \
        _Pragma("unroll")                                                           \
        for (int ks = 0; ks < 2; ks++) {                                            \
            const int kc = ks * 2;                                                  \
            uint32_t a[2][4];                                                       \
            _Pragma("unroll")                                                       \
            for (int i = 0; i < 2; i++) {                                           \
                int row = wm * 32 + i * 16 + (lane & 15);                           \
                int cch = kc + (lane >> 4);                                         \
                uint32_t ad = aSt + row * 64 + ((cch ^ ((row >> 1) & 3)) << 4);     \
                ldsm_x4(a[i][0], a[i][1], a[i][2], a[i][3], ad);                    \
            }                                                                       \
            _Pragma("unroll")                                                       \
            for (int j = 0; j < 8; j++) {                                           \
                int row = wn * 64 + j * 8 + (lane & 7);                             \
                int cch = kc + ((lane >> 3) & 1);                                   \
                uint32_t bd = bSt + row * 64 + ((cch ^ ((row >> 1) & 3)) << 4);     \
                uint32_t b0, b1;                                                    \
                ldsm_x2(b0, b1, bd);                                                \
                MMA16(acc[0][j], a[0], b0, b1);                                     \
                MMA16(acc[1][j], a[1], b0, b1);                                     \
            }                                                                       \
        }                                                                           \
    } while (0)

#define EPILOGUE(P0)                                                                \
    do {                                                                            \
        _Pragma("unroll")                                                           \
        for (int i = 0; i < 2; i++) {                                               \
            _Pragma("unroll")                                                       \
            for (int j = 0; j < 8; j++) {                                           \
                int rp = (P0) + wm * 32 + i * 16 + (lane >> 2);                     \
                int cg = colStart + wn * 64 + j * 8 + (lane & 3) * 2;               \
                __half2 h01 = __floats2half2_rn(acc[i][j][0], acc[i][j][1]);        \
                __half2 h23 = __floats2half2_rn(acc[i][j][2], acc[i][j][3]);        \
                *(__half2*)&g_scratch[(size_t)rp * C_OUT + cg] = h01;               \
                *(__half2*)&g_scratch[(size_t)(rp + 8) * C_OUT + cg] = h23;         \
            }                                                                       \
        }                                                                           \
    } while (0)

    LOAD_CHUNK(0, srowA, BthA);
    LOAD_CHUNK(1, srowA, BthA);
    LOAD_CHUNK(2, srowA, BthA);

    CP_WAIT(2); __syncthreads();
    COMPUTE(0); __syncthreads();
    LOAD_CHUNK(3, srowA, BthA);

    CP_WAIT(2); __syncthreads();
    COMPUTE(1); __syncthreads();
    LOAD_CHUNK(4, srowB, BthB);

    CP_WAIT(2); __syncthreads();
    COMPUTE(2); __syncthreads();
    LOAD_CHUNK(5, srowB, BthB);

    CP_WAIT(2); __syncthreads();
    COMPUTE(3);
    EPILOGUE(p0a);
#pragma unroll
    for (int i = 0; i < 2; i++)
#pragma unroll
        for (int j = 0; j < 8; j++)
#pragma unroll
            for (int q = 0; q < 4; q++) acc[i][j][q] = 0.f;
    __syncthreads();
    LOAD_CHUNK(6, srowB, BthB);

    CP_WAIT(2); __syncthreads();
    COMPUTE(4); __syncthreads();
    LOAD_CHUNK(7, srowB, BthB);

    CP_WAIT(2); __syncthreads();
    COMPUTE(5);

    CP_WAIT(1); __syncthreads();
    COMPUTE(6);

    CP_WAIT(0); __syncthreads();
    COMPUTE(7);

    if (hasB) EPILOGUE(p0b);
#undef LOAD_CHUNK
#undef COMPUTE
#undef EPILOGUE
}

// ---------------- K_cstats: combine + per-channel stats + last-block BN ----------------
#define SITES_PER_BLOCK 256
__global__ __launch_bounds__(256)
void k_cstats(const float* __restrict__ gamma, const float* __restrict__ beta, int N) {
    __shared__ int   sp[SITES_PER_BLOCK * TAPS];   // 4 KB
    __shared__ float ssum[C_OUT], ssq[C_OUT];
    __shared__ int   slast;
    const int tid = threadIdx.x;
    const int s0  = blockIdx.x * SITES_PER_BLOCK;

    for (int i = tid; i < C_OUT; i += 256) { ssum[i] = 0.f; ssq[i] = 0.f; }
    for (int i = tid; i < SITES_PER_BLOCK * TAPS; i += 256) {
        int site = s0 + (i >> 2);
        sp[i] = (site < N) ? g_pslot[(size_t)site * TAPS + (i & 3)] : -1;
    }
    __syncthreads();

    const int c4 = tid & 63, sr = tid >> 6;
    float ls0 = 0.f, ls1 = 0.f, ls2 = 0.f, ls3 = 0.f;
    float lq0 = 0.f, lq1 = 0.f, lq2 = 0.f, lq3 = 0.f;

    for (int it = 0; it < SITES_PER_BLOCK / 4; it++) {
        int sl = it * 4 + sr;
        float4 v = make_float4(0.f, 0.f, 0.f, 0.f);
#pragma unroll
        for (int t = 0; t < TAPS; t++) {
            int p = sp[sl * 4 + t];
            if (p >= 0) {
                float4 u = ld_scratch4(g_scratch + (size_t)p * C_OUT + c4 * 4);
                v.x += u.x; v.y += u.y; v.z += u.z; v.w += u.w;
            }
        }
        ls0 += v.x; ls1 += v.y; ls2 += v.z; ls3 += v.w;
        lq0 += v.x * v.x; lq1 += v.y * v.y; lq2 += v.z * v.z; lq3 += v.w * v.w;
    }
    atomicAdd(&ssum[c4 * 4 + 0], ls0);
    atomicAdd(&ssum[c4 * 4 + 1], ls1);
    atomicAdd(&ssum[c4 * 4 + 2], ls2);
    atomicAdd(&ssum[c4 * 4 + 3], ls3);
    atomicAdd(&ssq[c4 * 4 + 0], lq0);
    atomicAdd(&ssq[c4 * 4 + 1], lq1);
    atomicAdd(&ssq[c4 * 4 + 2], lq2);
    atomicAdd(&ssq[c4 * 4 + 3], lq3);
    __syncthreads();
    for (int i = tid; i < C_OUT; i += 256) {
        atomicAdd(&g_sum[i], ssum[i]);
        atomicAdd(&g_sumsq[i], ssq[i]);
    }

    // ---- last block computes BN params (folded k_bn) ----
    __syncthreads();
    if (tid == 0) {
        __threadfence();
        int done = atomicAdd(&g_ctr2, 1);
        slast = (done == (int)gridDim.x - 1);
    }
    __syncthreads();
    if (slast) {
        int c = tid;
        float cnt  = g_cnt;
        float mean = g_sum[c] / cnt;
        float var  = fmaxf(g_sumsq[c] / cnt - mean * mean, 0.f);
        float sc   = rsqrtf(var + BN_EPS) * gamma[c];
        float bi   = beta[c] - mean * sc;
        g_scale[c] = sc;
        g_bias[c]  = bi;
        g_sum[c]   = 0.f;
        g_sumsq[c] = 0.f;
        if (c == 0) { g_cnt = 0.f; g_ctr2 = 0; }
        if (c < TAPS) g_tap_count[c] = 0;
    }
}

// ---------------- K_final: recombine + BN + ReLU + mask -> y (streaming y stores) ------
__global__ __launch_bounds__(256)
void k_final(float* __restrict__ y, const float* __restrict__ mask, int N) {
    __shared__ int sp[SITES_PER_BLOCK * TAPS];
    const int tid = threadIdx.x;
    const int s0  = blockIdx.x * SITES_PER_BLOCK;

    for (int i = tid; i < SITES_PER_BLOCK * TAPS; i += 256) {
        int site = s0 + (i >> 2);
        sp[i] = (site < N) ? g_pslot[(size_t)site * TAPS + (i & 3)] : -1;
    }
    __syncthreads();

    const int c4 = tid & 63, sr = tid >> 6;
    const float4 sc = *(const float4*)&g_scale[c4 * 4];
    const float4 bi = *(const float4*)&g_bias[c4 * 4];

    for (int it = 0; it < SITES_PER_BLOCK / 4; it++) {
        int sl = it * 4 + sr;
        int site = s0 + sl;
        if (site >= N) continue;
        float4 v = make_float4(0.f, 0.f, 0.f, 0.f);
#pragma unroll
        for (int t = 0; t < TAPS; t++) {
            int p = sp[sl * 4 + t];
            if (p >= 0) {
                float4 u = ld_scratch4(g_scratch + (size_t)p * C_OUT + c4 * 4);
                v.x += u.x; v.y += u.y; v.z += u.z; v.w += u.w;
            }
        }
        float m = mask[site];
        v.x = fmaxf(fmaf(v.x, sc.x, bi.x), 0.f) * m;
        v.y = fmaxf(fmaf(v.y, sc.y, bi.y), 0.f) * m;
        v.z = fmaxf(fmaf(v.z, sc.z, bi.z), 0.f) * m;
        v.w = fmaxf(fmaf(v.w, sc.w, bi.w), 0.f) * m;
        // evict-first store: keep scratch resident in L2 for remaining gathers
        __stcs((float4*)&y[(size_t)site * C_OUT + c4 * 4], v);
    }
}

// ---------------- launch ----------------
extern "C" void kernel_launch(void* const* d_in, const int* in_sizes, int n_in,
                              void* d_out, int out_size) {
    const float* x         = (const float*)d_in[0];
    const float* W         = (const float*)d_in[1];
    const float* gamma     = (const float*)d_in[2];
    const float* beta      = (const float*)d_in[3];
    const int*   offset    = (const int*)d_in[4];
    const int*   out_index = (const int*)d_in[5];
    const float* mask      = (const float*)d_in[6];
    float*       out       = (float*)d_out;

    int N = in_sizes[4];
    if (N > N_MAX) N = N_MAX;

    cudaFuncSetAttribute(k_conv, cudaFuncAttributeMaxDynamicSharedMemorySize,
                         SMEM_BYTES);

    k_prep<<<512, 256>>>(x, W, offset, N);                                  // 0
    k_perm<<<256, 256>>>(offset, out_index, mask, N);                       // 1

    int tiles = (N + 127) / 128 + TAPS;   // upper bound incl. per-tap padding
    int pairTiles = (tiles + 1) / 2;
    k_conv<<<dim3(2, pairTiles), 256, SMEM_BYTES>>>();                      // 2

    int cb = (N + SITES_PER_BLOCK - 1) / SITES_PER_BLOCK;
    k_cstats<<<cb, 256>>>(gamma, beta, N);                                  // 3
    k_final<<<cb, 256>>>(out, mask, N);                                     // 4
}